// round 15
// baseline (speedup 1.0000x reference)
#include <cuda_runtime.h>

typedef unsigned long long ull;

#define NQ 10
#define LAYERS 4
#define DIM 784
#define DIM4 (DIM / 4)
#define NOUT 10
#define NGATES (LAYERS * NQ)

// Precomputed gate coefficients: for each (layer, qubit): {ar, ai, br, bi}
// Rot = [[a, b], [-conj(b), conj(a)]],
//   a = exp(-i(phi+omega)/2) cos(th/2),  b = -exp(+i(phi-omega)/2) sin(th/2)
__device__ float g_gates[NGATES * 4];

__global__ void precompute_gates_kernel(const float* __restrict__ qw) {
    int i = threadIdx.x;
    if (i < NGATES) {
        float phi = qw[i * 3 + 0], th = qw[i * 3 + 1], om = qw[i * 3 + 2];
        float s = sinf(th * 0.5f), c = cosf(th * 0.5f);
        float sp, cp, sm, cm;
        sincosf((phi + om) * 0.5f, &sp, &cp);
        sincosf((phi - om) * 0.5f, &sm, &cm);
        g_gates[i * 4 + 0] =  cp * c;
        g_gates[i * 4 + 1] = -sp * c;
        g_gates[i * 4 + 2] = -cm * s;
        g_gates[i * 4 + 3] = -sm * s;
    }
}

// ---------------- f32x2 helpers (FFMA2 only reachable via PTX) --------------
__device__ __forceinline__ ull pk(float a, float b) {
    ull r; asm("mov.b64 %0,{%1,%2};" : "=l"(r) : "f"(a), "f"(b)); return r;
}
__device__ __forceinline__ void upk(ull v, float& a, float& b) {
    asm("mov.b64 {%0,%1},%2;" : "=f"(a), "=f"(b) : "l"(v));
}
__device__ __forceinline__ ull swp(ull v) { float a, b; upk(v, a, b); return pk(b, a); }
__device__ __forceinline__ ull fma2(ull a, ull b, ull c) {
    ull d; asm("fma.rn.f32x2 %0,%1,%2,%3;" : "=l"(d) : "l"(a), "l"(b), "l"(c)); return d;
}
__device__ __forceinline__ ull mul2(ull a, ull b) {
    ull d; asm("mul.rn.f32x2 %0,%1,%2;" : "=l"(d) : "l"(a), "l"(b)); return d;
}
__device__ __forceinline__ ull add2(ull a, ull b) {
    ull d; asm("add.rn.f32x2 %0,%1,%2;" : "=l"(d) : "l"(a), "l"(b)); return d;
}

// complex multiply: (cr,ci) = (ar,ai)*(br,bi)
__device__ __forceinline__ void cmul(float ar, float ai, float br, float bi,
                                     float& cr, float& ci) {
    cr = fmaf(ar, br, -ai * bi);
    ci = fmaf(ar, bi,  ai * br);
}

// ---------------- generalized Rot gate, 2-warp team -------------------------
// Physical index y: bits[2:0] = pack idx p, bit3 = warp, bit4 = half,
// bits[9:5] = lane. Gate pairs sites along phys XOR mask V; logical-bit value
// at a site is parity(S & y).
template<unsigned V, unsigned S>
__device__ __forceinline__ void gate(ull* reP, ull* imP, const float* g,
                                     unsigned lane, unsigned wbit, unsigned tid,
                                     ull (*buf)[64]) {
    const float ar = g[0], ai = g[1], br = g[2], bi = g[3];
    constexpr unsigned VLANE = V >> 5;
    constexpr unsigned VL7   = V & 7u;
    constexpr bool     V3    = ((V >> 3) & 1u) != 0;
    constexpr bool     V4    = ((V >> 4) & 1u) != 0;
    constexpr unsigned SLANE = S >> 5;
    constexpr unsigned SL7   = S & 7u;
    constexpr bool     S3    = ((S >> 3) & 1u) != 0;
    constexpr bool     S4    = ((S >> 4) & 1u) != 0;

    unsigned par = (SLANE ? (unsigned)__popc(lane & SLANE) : 0u) ^ (S3 ? wbit : 0u);
    unsigned sgn = (par & 1u) << 31;
    float cmi0  = __uint_as_float(__float_as_uint(ai) ^ sgn);
    float cor0  = __uint_as_float(__float_as_uint(br) ^ sgn);
    float cmi0h = S4 ? -cmi0 : cmi0;
    float cor0h = S4 ? -cor0 : cor0;
    ull arP   = pk(ar, ar);
    ull biP   = pk(bi, bi);
    ull nbiP  = pk(-bi, -bi);
    ull cmiP0 = pk(cmi0, cmi0h), cmiP1 = pk(-cmi0, -cmi0h);
    ull corP0 = pk(cor0, cor0h), corP1 = pk(-cor0, -cor0h);

    auto site = [&](ull mre, ull mim, ull ore, ull oim, bool cls, ull& nre, ull& nim) {
        ull cip = cls ? cmiP1 : cmiP0;
        ull cin = cls ? cmiP0 : cmiP1;
        ull cop = cls ? corP1 : corP0;
        nre = fma2(arP, mre, fma2(cin, mim, fma2(cop, ore, mul2(nbiP, oim))));
        nim = fma2(arP, mim, fma2(cip, mre, fma2(cop, oim, mul2(biP, ore))));
    };

    if (V3) {
        // ---- cross-warp exchange via shared memory ----
#pragma unroll
        for (int k = 0; k < 8; k++) { buf[k][tid] = reP[k]; buf[8 + k][tid] = imP[k]; }
        __syncthreads();
        const unsigned ptid = (tid ^ 32u) ^ VLANE;
#pragma unroll
        for (int p = 0; p < 8; p++) {
            const int q = p ^ (int)VL7;
            ull ore = buf[q][ptid], oim = buf[8 + q][ptid];
            if (V4) { ore = swp(ore); oim = swp(oim); }
            const bool clsP = (__popc((unsigned)p & SL7) & 1) != 0;
            ull nre, nim;
            site(reP[p], imP[p], ore, oim, clsP, nre, nim);
            reP[p] = nre; imP[p] = nim;
        }
        __syncthreads();   // protect buffer before next reuse
    } else if (VLANE == 0) {
        // ---- local (in-thread) ----
#pragma unroll
        for (int p = 0; p < 8; p++) {
            const int q = p ^ (int)VL7;
            if (VL7 != 0 && q < p) continue;
            const bool clsP = (__popc((unsigned)p & SL7) & 1) != 0;
            const bool clsQ = (__popc((unsigned)q & SL7) & 1) != 0;
            if (VL7 == 0) {                        // partner = own pack, halves swapped
                ull ore = swp(reP[p]), oim = swp(imP[p]);
                ull nre, nim;
                site(reP[p], imP[p], ore, oim, clsP, nre, nim);
                reP[p] = nre; imP[p] = nim;
            } else {
                ull oreP = V4 ? swp(reP[q]) : reP[q];
                ull oimP = V4 ? swp(imP[q]) : imP[q];
                ull oreQ = V4 ? swp(reP[p]) : reP[p];
                ull oimQ = V4 ? swp(imP[p]) : imP[p];
                ull nre1, nim1, nre2, nim2;
                site(reP[p], imP[p], oreP, oimP, clsP, nre1, nim1);
                site(reP[q], imP[q], oreQ, oimQ, clsQ, nre2, nim2);
                reP[p] = nre1; imP[p] = nim1;
                reP[q] = nre2; imP[q] = nim2;
            }
        }
    } else {
        // ---- cross-lane shuffle ----
#pragma unroll
        for (int p = 0; p < 8; p++) {
            const int q = p ^ (int)VL7;
            if (VL7 != 0 && q < p) continue;
            const bool clsP = (__popc((unsigned)p & SL7) & 1) != 0;
            const bool clsQ = (__popc((unsigned)q & SL7) & 1) != 0;
            float a0, a1, b0, b1;
            upk(reP[q], a0, a1); upk(imP[q], b0, b1);
            float sa0 = __shfl_xor_sync(0xffffffffu, V4 ? a1 : a0, VLANE);
            float sa1 = __shfl_xor_sync(0xffffffffu, V4 ? a0 : a1, VLANE);
            float sb0 = __shfl_xor_sync(0xffffffffu, V4 ? b1 : b0, VLANE);
            float sb1 = __shfl_xor_sync(0xffffffffu, V4 ? b0 : b1, VLANE);
            ull oreP = pk(sa0, sa1), oimP = pk(sb0, sb1);
            if (VL7 == 0) {
                ull nre, nim;
                site(reP[p], imP[p], oreP, oimP, clsP, nre, nim);
                reP[p] = nre; imP[p] = nim;
            } else {
                float c0, c1, d0, d1;
                upk(reP[p], c0, c1); upk(imP[p], d0, d1);
                float ta0 = __shfl_xor_sync(0xffffffffu, V4 ? c1 : c0, VLANE);
                float ta1 = __shfl_xor_sync(0xffffffffu, V4 ? c0 : c1, VLANE);
                float tb0 = __shfl_xor_sync(0xffffffffu, V4 ? d1 : d0, VLANE);
                float tb1 = __shfl_xor_sync(0xffffffffu, V4 ? d0 : d1, VLANE);
                ull oreQ = pk(ta0, ta1), oimQ = pk(tb0, tb1);
                ull nre1, nim1, nre2, nim2;
                site(reP[p], imP[p], oreP, oimP, clsP, nre1, nim1);
                site(reP[q], imP[q], oreQ, oimQ, clsQ, nre2, nim2);
                reP[p] = nre1; imP[p] = nim1;
                reP[q] = nre2; imP[q] = nim2;
            }
        }
    }
}

__global__ __launch_bounds__(64, 10)
void qnet_kernel(const float* __restrict__ x,
                 const float* __restrict__ Wp,
                 const float* __restrict__ bp,
                 const float* __restrict__ Wo,
                 const float* __restrict__ bo,
                 float* __restrict__ out) {
    __shared__ float sg[NGATES * 4];
    __shared__ ull buf[16][64];
    __shared__ ull pxch[2][5];
    __shared__ ull zxch[2][5];

    const unsigned tid  = threadIdx.x;
    const unsigned lane = tid & 31u;
    const unsigned wbit = tid >> 5;

    for (int i = (int)tid; i < NGATES * 4; i += 64) sg[i] = g_gates[i];

    // ---------------- projection: h = tanh(x @ Wp^T + bp), 64 threads -------
    const ulonglong2* x2 = (const ulonglong2*)(x + (size_t)blockIdx.x * DIM);
    const ulonglong2* w2 = (const ulonglong2*)Wp;
    ull acc2[NQ];
#pragma unroll
    for (int q = 0; q < NQ; q++) acc2[q] = 0ull;
    for (int i = (int)tid; i < DIM4; i += 64) {
        ulonglong2 xv = x2[i];
#pragma unroll
        for (int q = 0; q < NQ; q++) {
            ulonglong2 wv = w2[q * DIM4 + i];
            acc2[q] = fma2(xv.x, wv.x, acc2[q]);
            acc2[q] = fma2(xv.y, wv.y, acc2[q]);
        }
    }
    ull accP[5];
#pragma unroll
    for (int k = 0; k < 5; k++) {
        float e0, o0, e1, o1;
        upk(acc2[2 * k], e0, o0);
        upk(acc2[2 * k + 1], e1, o1);
        accP[k] = pk(e0 + o0, e1 + o1);
    }
#pragma unroll
    for (int m = 16; m >= 1; m >>= 1)
#pragma unroll
        for (int k = 0; k < 5; k++)
            accP[k] = add2(accP[k], __shfl_xor_sync(0xffffffffu, accP[k], m));
    if (lane == 0) {
#pragma unroll
        for (int k = 0; k < 5; k++) pxch[wbit][k] = accP[k];
    }
    __syncthreads();                       // also publishes sg
#pragma unroll
    for (int k = 0; k < 5; k++) accP[k] = add2(accP[k], pxch[wbit ^ 1][k]);
    float acc[NQ];
#pragma unroll
    for (int k = 0; k < 5; k++) upk(accP[k], acc[2 * k], acc[2 * k + 1]);

    // ---------------- per-qubit states (RY embedding folded with layer-0 Rot)
    float alr[NQ], ali[NQ], ber[NQ], bei[NQ];
#pragma unroll
    for (int q = 0; q < NQ; q++) {
        float a = acc[q] + bp[q];
        float e = __expf(2.0f * a);                       // tanh = 1 - 2/(e^{2a}+1)
        float h = 1.0f - __fdividef(2.0f, e + 1.0f);
        float s, c;
        __sincosf(0.5f * h, &s, &c);
        const float ar = sg[q * 4 + 0], ai = sg[q * 4 + 1];
        const float br = sg[q * 4 + 2], bi = sg[q * 4 + 3];
        alr[q] = fmaf(ar, c,  br * s);
        ali[q] = fmaf(ai, c,  bi * s);
        ber[q] = fmaf(ar, s, -br * c);
        bei[q] = fmaf(bi, c, -ai * s);
    }

    // ---------------- product state, prefix-parity basis ---------------------
    // y: p=y[2:0], w=y3, half=y4, lane=y[9:5].
    // Logical: x0=p0, x1=p0^p1, x2=p1^p2, x3=p2^w, x4=w^half, x5=half^l0,
    //          x6=l1, x7=l2, x8=l3, x9=l4.
    float Tr = ((lane >> 1) & 1u) ? ber[6] : alr[6];
    float Ti = ((lane >> 1) & 1u) ? bei[6] : ali[6];
#pragma unroll
    for (int k = 2; k < 5; k++) {
        float fr = ((lane >> k) & 1u) ? ber[5 + k] : alr[5 + k];
        float fi = ((lane >> k) & 1u) ? bei[5 + k] : ali[5 + k];
        float nr, ni; cmul(Tr, Ti, fr, fi, nr, ni);
        Tr = nr; Ti = ni;
    }
    const bool l0 = (lane & 1u) != 0;
    const bool w1 = (wbit & 1u) != 0;
    // LA (half=0): T * f5(l0) * f4(w) ; LB (half=1): T * f5(~l0) * f4(~w)
    float t0r, t0i, t1r, t1i, LAr, LAi, LBr, LBi;
    cmul(Tr, Ti, l0 ? ber[5] : alr[5], l0 ? bei[5] : ali[5], t0r, t0i);
    cmul(t0r, t0i, w1 ? ber[4] : alr[4], w1 ? bei[4] : ali[4], LAr, LAi);
    cmul(Tr, Ti, l0 ? alr[5] : ber[5], l0 ? ali[5] : bei[5], t1r, t1i);
    cmul(t1r, t1i, w1 ? alr[4] : ber[4], w1 ? ali[4] : bei[4], LBr, LBi);
    // F01[p0,p1] = f0(p0)*f1(p0^p1) ; F23[p1,p2] = f2(p1^p2)*f3(p2^w)
    float F01r[4], F01i[4], F23r[4], F23i[4];
#pragma unroll
    for (int j = 0; j < 4; j++) {
        int p0 = j & 1, p1 = (j >> 1) & 1;
        float f0r = p0 ? ber[0] : alr[0], f0i = p0 ? bei[0] : ali[0];
        int x1b = p0 ^ p1;
        float f1r = x1b ? ber[1] : alr[1], f1i = x1b ? bei[1] : ali[1];
        cmul(f0r, f0i, f1r, f1i, F01r[j], F01i[j]);
        int q1 = j & 1, q2 = (j >> 1) & 1;           // (p1, p2)
        int x2b = q1 ^ q2;
        float f2r = x2b ? ber[2] : alr[2], f2i = x2b ? bei[2] : ali[2];
        int x3b = q2 ^ (int)wbit;
        float f3r = x3b ? ber[3] : alr[3], f3i = x3b ? bei[3] : ali[3];
        cmul(f2r, f2i, f3r, f3i, F23r[j], F23i[j]);
    }
    ull reP[8], imP[8];
#pragma unroll
    for (int p = 0; p < 8; p++) {
        const int j01 = p & 3;                         // (p0,p1)
        const int j23 = (p >> 1) & 3;                  // (p1,p2)
        float abr, abi;
        cmul(F01r[j01], F01i[j01], F23r[j23], F23i[j23], abr, abi);
        float lr, li, hr, hi;
        cmul(abr, abi, LAr, LAi, lr, li);
        cmul(abr, abi, LBr, LBi, hr, hi);
        reP[p] = pk(lr, hr);
        imP[p] = pk(li, hi);
    }

    // ---------------- layers 1..3 (same masks; storage reinterpreted) --------
#define G(l, q, V, S) gate<V, S>(reP, imP, sg + ((l) * NQ + (q)) * 4, lane, wbit, tid, buf)
    G(1,0,0x001,0x3E1); G(1,1,0x002,0x002); G(1,2,0x004,0x004); G(1,3,0x008,0x008); G(1,4,0x010,0x010);
    G(1,5,0x060,0x020); G(1,6,0x0C0,0x060); G(1,7,0x180,0x0E0); G(1,8,0x300,0x1E0); G(1,9,0x201,0x3E0);
    G(2,0,0x003,0x2BE); G(2,1,0x006,0x3E3); G(2,2,0x00C,0x3E7); G(2,3,0x018,0x3EF); G(2,4,0x070,0x3FF);
    G(2,5,0x0A0,0x3DF); G(2,6,0x140,0x3BF); G(2,7,0x280,0x35F); G(2,8,0x101,0x2BF); G(2,9,0x202,0x15F);
    G(3,0,0x005,0x0CB); G(3,1,0x00A,0x15D); G(3,2,0x014,0x2BA); G(3,3,0x068,0x155); G(3,4,0x0D0,0x2AA);
    G(3,5,0x1E0,0x175); G(3,6,0x3C0,0x2CA); G(3,7,0x381,0x195); G(3,8,0x303,0x32A); G(3,9,0x207,0x275);
#undef G

    // ---------------- probabilities + 8-point Walsh-Hadamard ----------------
    ull W[8];
#pragma unroll
    for (int p = 0; p < 8; p++)
        W[p] = fma2(reP[p], reP[p], mul2(imP[p], imP[p]));
    const ull NEG1 = pk(-1.0f, -1.0f);
#pragma unroll
    for (int k = 1; k < 8; k <<= 1) {
#pragma unroll
        for (int i = 0; i < 8; i++) {
            if (!(i & k)) {
                ull a = W[i], b = W[i | k];
                W[i]     = add2(a, b);
                W[i | k] = fma2(NEG1, b, a);
            }
        }
    }

    // Z rows in prefix-parity basis (10-bit masks, decomposed per new layout)
    constexpr unsigned ZRS[NQ] = {0x36D, 0x196, 0x32C, 0x279, 0x0D3,
                                  0x1A6, 0x36C, 0x2F9, 0x1D3, 0x3A6};
    float z[NQ];
#pragma unroll
    for (int q = 0; q < NQ; q++) {
        float lo, hi;
        upk(W[ZRS[q] & 7u], lo, hi);
        float s = ((ZRS[q] >> 4) & 1u) ? (lo - hi) : (lo + hi);
        unsigned p2 = ((unsigned)__popc(lane & (ZRS[q] >> 5)) ^
                       (((ZRS[q] >> 3) & 1u) ? wbit : 0u)) & 1u;
        z[q] = __uint_as_float(__float_as_uint(s) ^ (p2 << 31));
    }
    ull zPk[5];
#pragma unroll
    for (int k = 0; k < 5; k++) zPk[k] = pk(z[2 * k], z[2 * k + 1]);
#pragma unroll
    for (int m = 16; m >= 1; m >>= 1)
#pragma unroll
        for (int k = 0; k < 5; k++)
            zPk[k] = add2(zPk[k], __shfl_xor_sync(0xffffffffu, zPk[k], m));
    if (lane == 0) {
#pragma unroll
        for (int k = 0; k < 5; k++) zxch[wbit][k] = zPk[k];
    }
    __syncthreads();

    // ---------------- output projection (warp 0) -----------------------------
    if (wbit == 0) {
#pragma unroll
        for (int k = 0; k < 5; k++) zPk[k] = add2(zPk[k], zxch[1][k]);
#pragma unroll
        for (int k = 0; k < 5; k++) upk(zPk[k], z[2 * k], z[2 * k + 1]);
        if (lane < NOUT) {
            float o = bo[lane];
#pragma unroll
            for (int q = 0; q < NQ; q++)
                o = fmaf(z[q], Wo[lane * NQ + q], o);
            out[(size_t)blockIdx.x * NOUT + lane] = o;
        }
    }
}

extern "C" void kernel_launch(void* const* d_in, const int* in_sizes, int n_in,
                              void* d_out, int out_size) {
    const float* x  = (const float*)d_in[0];   // (B, 784)
    const float* Wp = (const float*)d_in[1];   // (10, 784)
    const float* bp = (const float*)d_in[2];   // (10,)
    const float* qw = (const float*)d_in[3];   // (4, 10, 3)
    const float* Wo = (const float*)d_in[4];   // (10, 10)
    const float* bo = (const float*)d_in[5];   // (10,)
    float* out = (float*)d_out;                // (B, 10)

    const int batch = in_sizes[0] / DIM;

    precompute_gates_kernel<<<1, 64>>>(qw);

    // one 64-thread block (2-warp team) per batch element
    qnet_kernel<<<batch, 64>>>(x, Wp, bp, Wo, bo, out);
}

// round 16
// speedup vs baseline: 1.1962x; 1.1962x over previous
#include <cuda_runtime.h>

typedef unsigned long long ull;

#define NQ 10
#define LAYERS 4
#define DIM 784
#define DIM4 (DIM / 4)
#define NOUT 10
#define NGATES (LAYERS * NQ)

// Precomputed gate coefficients: for each (layer, qubit): {ar, ai, br, bi}
// Rot = [[a, b], [-conj(b), conj(a)]],
//   a = exp(-i(phi+omega)/2) cos(th/2),  b = -exp(+i(phi-omega)/2) sin(th/2)
__device__ float g_gates[NGATES * 4];

__global__ void precompute_gates_kernel(const float* __restrict__ qw) {
    int i = threadIdx.x;
    if (i < NGATES) {
        float phi = qw[i * 3 + 0], th = qw[i * 3 + 1], om = qw[i * 3 + 2];
        float s = sinf(th * 0.5f), c = cosf(th * 0.5f);
        float sp, cp, sm, cm;
        sincosf((phi + om) * 0.5f, &sp, &cp);
        sincosf((phi - om) * 0.5f, &sm, &cm);
        g_gates[i * 4 + 0] =  cp * c;
        g_gates[i * 4 + 1] = -sp * c;
        g_gates[i * 4 + 2] = -cm * s;
        g_gates[i * 4 + 3] = -sm * s;
    }
}

// ---------------- f32x2 helpers (FFMA2 only reachable via PTX) --------------
__device__ __forceinline__ ull pk(float a, float b) {
    ull r; asm("mov.b64 %0,{%1,%2};" : "=l"(r) : "f"(a), "f"(b)); return r;
}
__device__ __forceinline__ void upk(ull v, float& a, float& b) {
    asm("mov.b64 {%0,%1},%2;" : "=f"(a), "=f"(b) : "l"(v));
}
__device__ __forceinline__ ull swp(ull v) { float a, b; upk(v, a, b); return pk(b, a); }
__device__ __forceinline__ ull fma2(ull a, ull b, ull c) {
    ull d; asm("fma.rn.f32x2 %0,%1,%2,%3;" : "=l"(d) : "l"(a), "l"(b), "l"(c)); return d;
}
__device__ __forceinline__ ull mul2(ull a, ull b) {
    ull d; asm("mul.rn.f32x2 %0,%1,%2;" : "=l"(d) : "l"(a), "l"(b)); return d;
}
__device__ __forceinline__ ull add2(ull a, ull b) {
    ull d; asm("add.rn.f32x2 %0,%1,%2;" : "=l"(d) : "l"(a), "l"(b)); return d;
}

// complex multiply: (cr,ci) = (ar,ai)*(br,bi)
__device__ __forceinline__ void cmul(float ar, float ai, float br, float bi,
                                     float& cr, float& ci) {
    cr = fmaf(ar, br, -ai * bi);
    ci = fmaf(ar, bi,  ai * br);
}

// ---------------- generalized Rot gate --------------------------------------
// Physical index y: bits[3:0] = pack idx p, bit4 = half, bits[9:5] = lane.
// Gate pairs sites along phys XOR mask V; logical-bit value at a site is
// parity(S & y).
template<unsigned V, unsigned S>
__device__ __forceinline__ void gate(ull* reP, ull* imP, const float* g, unsigned lane) {
    const float ar = g[0], ai = g[1], br = g[2], bi = g[3];
    constexpr unsigned VLANE = V >> 5;
    constexpr unsigned VL15  = V & 15u;
    constexpr bool     V4    = ((V >> 4) & 1u) != 0;
    constexpr unsigned SLANE = S >> 5;
    constexpr unsigned SL15  = S & 15u;
    constexpr bool     S4    = ((S >> 4) & 1u) != 0;

    unsigned sgn = SLANE ? ((unsigned)(__popc(lane & SLANE) & 1) << 31) : 0u;
    float cmi0  = __uint_as_float(__float_as_uint(ai) ^ sgn);
    float cor0  = __uint_as_float(__float_as_uint(br) ^ sgn);
    float cmi0h = S4 ? -cmi0 : cmi0;
    float cor0h = S4 ? -cor0 : cor0;
    ull arP   = pk(ar, ar);
    ull biP   = pk(bi, bi);
    ull nbiP  = pk(-bi, -bi);
    ull cmiP0 = pk(cmi0, cmi0h), cmiP1 = pk(-cmi0, -cmi0h);
    ull corP0 = pk(cor0, cor0h), corP1 = pk(-cor0, -cor0h);

    auto site = [&](ull mre, ull mim, ull ore, ull oim, bool cls, ull& nre, ull& nim) {
        ull cip = cls ? cmiP1 : cmiP0;
        ull cin = cls ? cmiP0 : cmiP1;
        ull cop = cls ? corP1 : corP0;
        nre = fma2(arP, mre, fma2(cin, mim, fma2(cop, ore, mul2(nbiP, oim))));
        nim = fma2(arP, mim, fma2(cip, mre, fma2(cop, oim, mul2(biP, ore))));
    };

#pragma unroll
    for (int p = 0; p < 16; p++) {
        const int q = p ^ (int)VL15;
        if (VL15 != 0 && q < p) continue;
        const bool clsP = (__popc((unsigned)p & SL15) & 1) != 0;
        const bool clsQ = (__popc((unsigned)q & SL15) & 1) != 0;
        if (VLANE == 0) {
            if (VL15 == 0) {
                ull ore = swp(reP[p]), oim = swp(imP[p]);
                ull nre, nim;
                site(reP[p], imP[p], ore, oim, clsP, nre, nim);
                reP[p] = nre; imP[p] = nim;
            } else {
                ull oreP = V4 ? swp(reP[q]) : reP[q];
                ull oimP = V4 ? swp(imP[q]) : imP[q];
                ull oreQ = V4 ? swp(reP[p]) : reP[p];
                ull oimQ = V4 ? swp(imP[p]) : imP[p];
                ull nre1, nim1, nre2, nim2;
                site(reP[p], imP[p], oreP, oimP, clsP, nre1, nim1);
                site(reP[q], imP[q], oreQ, oimQ, clsQ, nre2, nim2);
                reP[p] = nre1; imP[p] = nim1;
                reP[q] = nre2; imP[q] = nim2;
            }
        } else {
            float a0, a1, b0, b1;
            upk(reP[q], a0, a1); upk(imP[q], b0, b1);
            float sa0 = __shfl_xor_sync(0xffffffffu, V4 ? a1 : a0, VLANE);
            float sa1 = __shfl_xor_sync(0xffffffffu, V4 ? a0 : a1, VLANE);
            float sb0 = __shfl_xor_sync(0xffffffffu, V4 ? b1 : b0, VLANE);
            float sb1 = __shfl_xor_sync(0xffffffffu, V4 ? b0 : b1, VLANE);
            ull oreP = pk(sa0, sa1), oimP = pk(sb0, sb1);
            if (VL15 == 0) {
                ull nre, nim;
                site(reP[p], imP[p], oreP, oimP, clsP, nre, nim);
                reP[p] = nre; imP[p] = nim;
            } else {
                float c0, c1, d0, d1;
                upk(reP[p], c0, c1); upk(imP[p], d0, d1);
                float ta0 = __shfl_xor_sync(0xffffffffu, V4 ? c1 : c0, VLANE);
                float ta1 = __shfl_xor_sync(0xffffffffu, V4 ? c0 : c1, VLANE);
                float tb0 = __shfl_xor_sync(0xffffffffu, V4 ? d1 : d0, VLANE);
                float tb1 = __shfl_xor_sync(0xffffffffu, V4 ? d0 : d1, VLANE);
                ull oreQ = pk(ta0, ta1), oimQ = pk(tb0, tb1);
                ull nre1, nim1, nre2, nim2;
                site(reP[p], imP[p], oreP, oimP, clsP, nre1, nim1);
                site(reP[q], imP[q], oreQ, oimQ, clsQ, nre2, nim2);
                reP[p] = nre1; imP[p] = nim1;
                reP[q] = nre2; imP[q] = nim2;
            }
        }
    }
}

__global__ __launch_bounds__(256, 2)
void qnet_kernel(const float* __restrict__ x,
                 const float* __restrict__ Wp,
                 const float* __restrict__ bp,
                 const float* __restrict__ Wo,
                 const float* __restrict__ bo,
                 float* __restrict__ out,
                 int batch) {
    __shared__ float sg[NGATES * 4];
    for (int i = threadIdx.x; i < NGATES * 4; i += blockDim.x) sg[i] = g_gates[i];
    __syncthreads();

    const int warp = (int)((blockIdx.x * blockDim.x + threadIdx.x) >> 5);
    const unsigned lane = threadIdx.x & 31u;
    if (warp >= batch) return;

    // ---------------- projection: h = tanh(x @ Wp^T + bp) ------------------
    // float4-wide loads reinterpreted as 2x f32x2 -> fma2 accumulation.
    const ulonglong2* x2 = (const ulonglong2*)(x + (size_t)warp * DIM);
    const ulonglong2* w2 = (const ulonglong2*)Wp;
    ull acc2[NQ];
#pragma unroll
    for (int q = 0; q < NQ; q++) acc2[q] = 0ull;
    for (int i = (int)lane; i < DIM4; i += 32) {
        ulonglong2 xv = x2[i];
#pragma unroll
        for (int q = 0; q < NQ; q++) {
            ulonglong2 wv = w2[q * DIM4 + i];
            acc2[q] = fma2(xv.x, wv.x, acc2[q]);
            acc2[q] = fma2(xv.y, wv.y, acc2[q]);
        }
    }
    // combine even/odd halves, then packed butterfly over lanes
    ull accP[5];
#pragma unroll
    for (int k = 0; k < 5; k++) {
        float e0, o0, e1, o1;
        upk(acc2[2 * k], e0, o0);
        upk(acc2[2 * k + 1], e1, o1);
        accP[k] = pk(e0 + o0, e1 + o1);
    }
#pragma unroll
    for (int m = 16; m >= 1; m >>= 1)
#pragma unroll
        for (int k = 0; k < 5; k++)
            accP[k] = add2(accP[k], __shfl_xor_sync(0xffffffffu, accP[k], m));
    float acc[NQ];
#pragma unroll
    for (int k = 0; k < 5; k++) upk(accP[k], acc[2 * k], acc[2 * k + 1]);

    // ---------------- per-qubit states (RY embedding folded with layer-0 Rot)
    float alr[NQ], ali[NQ], ber[NQ], bei[NQ];
#pragma unroll
    for (int q = 0; q < NQ; q++) {
        float a = acc[q] + bp[q];
        float e = __expf(2.0f * a);                       // tanh = 1 - 2/(e^{2a}+1)
        float h = 1.0f - __fdividef(2.0f, e + 1.0f);
        float s, c;
        __sincosf(0.5f * h, &s, &c);
        const float ar = sg[q * 4 + 0], ai = sg[q * 4 + 1];
        const float br = sg[q * 4 + 2], bi = sg[q * 4 + 3];
        alr[q] = fmaf(ar, c,  br * s);
        ali[q] = fmaf(ai, c,  bi * s);
        ber[q] = fmaf(ar, s, -br * c);
        bei[q] = fmaf(bi, c, -ai * s);
    }

    // ---------------- product state in prefix-parity basis -------------------
    // Storage index y: p = y[3:0], half = y4, lane = y[9:5].
    // Logical bits: x0=y0, x1=y0^y1, x2=y1^y2, x3=y2^y3, x4=y3^y4, x5=y4^y5,
    //               x6..x9 = y6..y9.
    float Lr = ((lane >> 1) & 1u) ? ber[6] : alr[6];
    float Li = ((lane >> 1) & 1u) ? bei[6] : ali[6];
#pragma unroll
    for (int k = 2; k < 5; k++) {
        float fr = ((lane >> k) & 1u) ? ber[5 + k] : alr[5 + k];
        float fi = ((lane >> k) & 1u) ? bei[5 + k] : ali[5 + k];
        float nr, ni; cmul(Lr, Li, fr, fi, nr, ni);
        Lr = nr; Li = ni;
    }
    // f5(h ^ lane0)
    const bool l0 = (lane & 1u) != 0;
    float f5ar = l0 ? ber[5] : alr[5], f5ai = l0 ? bei[5] : ali[5];
    float f5br = l0 ? alr[5] : ber[5], f5bi = l0 ? ali[5] : bei[5];
    float LAr, LAi, LBr, LBi;
    cmul(Lr, Li, f5ar, f5ai, LAr, LAi);
    cmul(Lr, Li, f5br, f5bi, LBr, LBi);
    // M0[t] = f4(t)*LA (half0, x4=p3^0); M1[t] = f4(t^1)*LB (half1)
    float M0r[2], M0i[2], M1r[2], M1i[2];
    cmul(alr[4], ali[4], LAr, LAi, M0r[0], M0i[0]);
    cmul(ber[4], bei[4], LAr, LAi, M0r[1], M0i[1]);
    cmul(ber[4], bei[4], LBr, LBi, M1r[0], M1i[0]);
    cmul(alr[4], ali[4], LBr, LBi, M1r[1], M1i[1]);
    // A[j] = f0(j0)*f1(j0^j1) ; Bv[k] = f2(k0)*f3(k1)
    float Ar[4], Ai[4], Bvr[4], Bvi[4];
#pragma unroll
    for (int j = 0; j < 4; j++) {
        int b0 = j & 1, b1 = (j ^ (j >> 1)) & 1;
        float f0r = b0 ? ber[0] : alr[0], f0i = b0 ? bei[0] : ali[0];
        float f1r = b1 ? ber[1] : alr[1], f1i = b1 ? bei[1] : ali[1];
        cmul(f0r, f0i, f1r, f1i, Ar[j], Ai[j]);
        int c0 = j & 1, c1 = (j >> 1) & 1;
        float f2r = c0 ? ber[2] : alr[2], f2i = c0 ? bei[2] : ali[2];
        float f3r = c1 ? ber[3] : alr[3], f3i = c1 ? bei[3] : ali[3];
        cmul(f2r, f2i, f3r, f3i, Bvr[j], Bvi[j]);
    }
    ull reP[16], imP[16];
#pragma unroll
    for (int p = 0; p < 16; p++) {
        const int j = p & 3;
        const int a = ((p >> 1) ^ (p >> 2)) & 1;
        const int b = ((p >> 2) ^ (p >> 3)) & 1;
        const int k = a | (b << 1);
        const int p3 = (p >> 3) & 1;
        float abr, abi;
        cmul(Ar[j], Ai[j], Bvr[k], Bvi[k], abr, abi);
        float lr, li, hr, hi;
        cmul(abr, abi, M0r[p3], M0i[p3], lr, li);
        cmul(abr, abi, M1r[p3], M1i[p3], hr, hi);
        reP[p] = pk(lr, hr);
        imP[p] = pk(li, hi);
    }

    // ---------------- layers 1..3 (masks in prefix-parity basis) -------------
    // Gates within a layer act on distinct logical qubits -> they commute.
    // Interleave local (fma-heavy) and cross-lane (shfl-heavy) gates so both
    // pipes see smooth demand instead of alternating saturation bursts.
#define G(l, q, V, S) gate<V, S>(reP, imP, sg + ((l) * NQ + (q)) * 4, lane)
    // layer 1: locals q0-q4, cross q5-q9 -> L,X,L,X,...
    G(1,0,0x001,0x3E1); G(1,5,0x060,0x020);
    G(1,1,0x002,0x002); G(1,6,0x0C0,0x060);
    G(1,2,0x004,0x004); G(1,7,0x180,0x0E0);
    G(1,3,0x008,0x008); G(1,8,0x300,0x1E0);
    G(1,4,0x010,0x010); G(1,9,0x201,0x3E0);
    // layer 2: locals q0-q3, cross q4-q9
    G(2,0,0x003,0x2BE); G(2,4,0x070,0x3FF);
    G(2,1,0x006,0x3E3); G(2,5,0x0A0,0x3DF);
    G(2,2,0x00C,0x3E7); G(2,6,0x140,0x3BF);
    G(2,3,0x018,0x3EF); G(2,7,0x280,0x35F);
    G(2,8,0x101,0x2BF); G(2,9,0x202,0x15F);
    // layer 3: locals q0-q2, cross q3-q9
    G(3,0,0x005,0x0CB); G(3,3,0x068,0x155);
    G(3,1,0x00A,0x15D); G(3,4,0x0D0,0x2AA);
    G(3,2,0x014,0x2BA); G(3,5,0x1E0,0x175);
    G(3,6,0x3C0,0x2CA); G(3,7,0x381,0x195);
    G(3,8,0x303,0x32A); G(3,9,0x207,0x275);
#undef G

    // ---------------- probabilities + Walsh-Hadamard parity sums ------------
    // W[m] = sum_p (-1)^parity(p & m) * pw[p]  (packed lo/hi halves separately)
    ull W[16];
#pragma unroll
    for (int p = 0; p < 16; p++)
        W[p] = fma2(reP[p], reP[p], mul2(imP[p], imP[p]));
    const ull NEG1 = pk(-1.0f, -1.0f);
#pragma unroll
    for (int k = 1; k < 16; k <<= 1) {
#pragma unroll
        for (int i = 0; i < 16; i++) {
            if (!(i & k)) {
                ull a = W[i], b = W[i | k];
                W[i]     = add2(a, b);
                W[i | k] = fma2(NEG1, b, a);
            }
        }
    }

    // Z rows in prefix-parity basis
    constexpr unsigned ZRS[NQ] = {0x36D, 0x196, 0x32C, 0x279, 0x0D3,
                                  0x1A6, 0x36C, 0x2F9, 0x1D3, 0x3A6};
    float z[NQ];
#pragma unroll
    for (int q = 0; q < NQ; q++) {
        float lo, hi;
        upk(W[ZRS[q] & 15u], lo, hi);
        float s = ((ZRS[q] >> 4) & 1u) ? (lo - hi) : (lo + hi);
        unsigned zs = ((unsigned)(__popc(lane & (ZRS[q] >> 5)) & 1)) << 31;
        z[q] = __uint_as_float(__float_as_uint(s) ^ zs);
    }
    // packed butterfly reduction over lanes
    ull zPk[5];
#pragma unroll
    for (int k = 0; k < 5; k++) zPk[k] = pk(z[2 * k], z[2 * k + 1]);
#pragma unroll
    for (int m = 16; m >= 1; m >>= 1)
#pragma unroll
        for (int k = 0; k < 5; k++)
            zPk[k] = add2(zPk[k], __shfl_xor_sync(0xffffffffu, zPk[k], m));
#pragma unroll
    for (int k = 0; k < 5; k++) upk(zPk[k], z[2 * k], z[2 * k + 1]);

    // ---------------- output projection --------------------------------------
    if (lane < NOUT) {
        float o = bo[lane];
#pragma unroll
        for (int q = 0; q < NQ; q++)
            o = fmaf(z[q], Wo[lane * NQ + q], o);
        out[(size_t)warp * NOUT + lane] = o;
    }
}

extern "C" void kernel_launch(void* const* d_in, const int* in_sizes, int n_in,
                              void* d_out, int out_size) {
    const float* x  = (const float*)d_in[0];   // (B, 784)
    const float* Wp = (const float*)d_in[1];   // (10, 784)
    const float* bp = (const float*)d_in[2];   // (10,)
    const float* qw = (const float*)d_in[3];   // (4, 10, 3)
    const float* Wo = (const float*)d_in[4];   // (10, 10)
    const float* bo = (const float*)d_in[5];   // (10,)
    float* out = (float*)d_out;                // (B, 10)

    const int batch = in_sizes[0] / DIM;

    precompute_gates_kernel<<<1, 64>>>(qw);

    const int threads = 256;                   // 8 warps/block, 2 blocks/SM — proven best
    const int warps_per_block = threads / 32;
    const int blocks = (batch + warps_per_block - 1) / warps_per_block;
    qnet_kernel<<<blocks, threads>>>(x, Wp, bp, Wo, bo, out, batch);
}